// round 4
// baseline (speedup 1.0000x reference)
#include <cuda_runtime.h>

#define TPB 640
#define NBLK 1024

typedef unsigned long long ull;

// ---- packed f32x2 helpers ----
__device__ __forceinline__ ull pk(float a, float b) {
    ull r; asm("mov.b64 %0,{%1,%2};" : "=l"(r) : "f"(a), "f"(b)); return r;
}
__device__ __forceinline__ void fma2(ull& d, ull a, ull b) {
    asm("fma.rn.f32x2 %0,%1,%2,%0;" : "+l"(d) : "l"(a), "l"(b));
}
__device__ __forceinline__ float2 upk(ull v) {
    float2 f; asm("mov.b64 {%0,%1},%2;" : "=f"(f.x), "=f"(f.y) : "l"(v)); return f;
}

// ---- dynamic smem layout (float offsets) ----
#define H0    0            // 12x34x34 padded activation ping (13872)
#define H1    13872        // pong; later transposed tail weights
#define TWS   H1           // [ky*9+kx][oc][ic56] (13608)
#define R2    27744
// phase A
#define XP    (R2)         // 3x36x36 padded input (3888)
#define HWS   (R2+3888)    // head weights padded [56][76] (4256)
#define HEADB (R2+8144)
#define HEADA (R2+8200)
#define B0W   (R2+8256)    // transposed [d56][12] (672)
#define B0B   (R2+8928)
#define B0A   (R2+8940)
// phase B
#define WSC   (R2)         // transposed [ic12][k9][oc12] (1296)
#define BSC   (R2+1296)
#define ASC   (R2+1308)
// phase C/D
#define GBUF  (R2)         // g strip [12 rows][36 x][60 ic-pad] (25920); also reduce scratch
#define B6B   (R2+25920)
#define B6A   (R2+25976)
#define TAILB (R2+26032)
#define B6W   (R2+26048)   // [oc56][12] (672)
#define SMEM_FLOATS (R2+26720)
#define SMEM_BYTES  (SMEM_FLOATS*4)

// ================= Phase B: 3x3 conv 12->12, 2 rows/thread, f32x2 (512 active threads) =================
template<bool ACT>
__device__ __forceinline__ void conv3x3_12(float* sm, int inOff, int outOff,
    const float* __restrict__ wg, const float* __restrict__ bg,
    const float* __restrict__ ag)
{
    const int tid = threadIdx.x;
    // stage weights transposed: [ic][k][oc]
    for (int i = tid; i < 1296; i += TPB) {
        int oc = i % 12, k = (i / 12) % 9, ic = i / 108;
        sm[WSC + ic * 108 + k * 12 + oc] = wg[(oc * 12 + ic) * 9 + k];
    }
    if (tid < 12) { sm[BSC + tid] = bg[tid]; if (ACT) sm[ASC + tid] = ag[tid]; }
    __syncthreads();

    if (tid < 512) {
        const int xx = tid & 31;
        const int y0 = (tid >> 5) * 2;

        ull acc[2][6];
#pragma unroll
        for (int j = 0; j < 2; j++)
#pragma unroll
            for (int p = 0; p < 6; p++)
                acc[j][p] = pk(sm[BSC + 2 * p], sm[BSC + 2 * p + 1]);

        for (int ic = 0; ic < 12; ic++) {
            float win[4][3];
#pragma unroll
            for (int ry = 0; ry < 4; ry++)
#pragma unroll
                for (int cx = 0; cx < 3; cx++)
                    win[ry][cx] = sm[inOff + (ic * 34 + y0 + ry) * 34 + xx + cx];
#pragma unroll
            for (int k = 0; k < 9; k++) {
                const int ky = k / 3, kx = k % 3;
                const ulonglong2* wp = (const ulonglong2*)&sm[WSC + ic * 108 + k * 12];
                const ulonglong2 wA = wp[0], wB = wp[1], wC = wp[2];
#pragma unroll
                for (int j = 0; j < 2; j++) {
                    const float v = win[j + ky][kx];
                    const ull vv = pk(v, v);
                    fma2(acc[j][0], vv, wA.x); fma2(acc[j][1], vv, wA.y);
                    fma2(acc[j][2], vv, wB.x); fma2(acc[j][3], vv, wB.y);
                    fma2(acc[j][4], vv, wC.x); fma2(acc[j][5], vv, wC.y);
                }
            }
        }
        __syncthreads();
#pragma unroll
        for (int j = 0; j < 2; j++)
#pragma unroll
            for (int p = 0; p < 6; p++) {
                float2 v = upk(acc[j][p]);
                float v0 = v.x, v1 = v.y;
                if (ACT) {
                    v0 = (v0 >= 0.f) ? v0 : sm[ASC + 2 * p] * v0;
                    v1 = (v1 >= 0.f) ? v1 : sm[ASC + 2 * p + 1] * v1;
                }
                sm[outOff + ((2 * p) * 34 + y0 + j + 1) * 34 + xx + 1] = v0;
                sm[outOff + ((2 * p + 1) * 34 + y0 + j + 1) * 34 + xx + 1] = v1;
            }
    } else {
        __syncthreads();
    }
    __syncthreads();
}

// ================= Phase D worker: one parity class, ic4 range, rolling row window =================
template<int PYR, int PXC>
__device__ __forceinline__ void deconv_cls(const float* sm, int lane, int cs, int ce,
                                           ull (&acc)[8][3])
{
    constexpr int A = PYR ? 4 : 5;   // #ky taps
    constexpr int C = PXC ? 4 : 5;   // #kx taps
    for (int ic4 = cs; ic4 < ce; ic4++) {
        const int gofs = ic4 * 4;
#pragma unroll
        for (int c = 0; c < C; c++) {
            const int kx = PXC + 2 * c;
            const int d  = 4 - c;
            const float* gb = &sm[GBUF + (lane + d) * 60 + gofs];
            ulonglong2 Gw[8];
#pragma unroll
            for (int rr = 4; rr <= 11; rr++)
                Gw[rr & 7] = *(const ulonglong2*)&gb[rr * 36 * 60];
#pragma unroll
            for (int a = 0; a < A; a++) {
                const int ky = PYR + 2 * a;
                const ulonglong2 w0 = *(const ulonglong2*)&sm[TWS + ((ky * 9 + kx) * 3 + 0) * 56 + gofs];
                const ulonglong2 w1 = *(const ulonglong2*)&sm[TWS + ((ky * 9 + kx) * 3 + 1) * 56 + gofs];
                const ulonglong2 w2 = *(const ulonglong2*)&sm[TWS + ((ky * 9 + kx) * 3 + 2) * 56 + gofs];
#pragma unroll
                for (int t = 0; t < 8; t++) {
                    const ulonglong2 g = Gw[(t + 4 - a) & 7];
                    fma2(acc[t][0], g.x, w0.x); fma2(acc[t][0], g.y, w0.y);
                    fma2(acc[t][1], g.x, w1.x); fma2(acc[t][1], g.y, w1.y);
                    fma2(acc[t][2], g.x, w2.x); fma2(acc[t][2], g.y, w2.y);
                }
                if (a < A - 1)
                    Gw[(3 - a) & 7] = *(const ulonglong2*)&gb[(3 - a) * 36 * 60];
            }
        }
    }
}

__global__ __launch_bounds__(TPB, 1)
void fsrcnn_fused_kernel(
    const float* __restrict__ x,
    const float* __restrict__ head_w, const float* __restrict__ head_b, const float* __restrict__ head_a,
    const float* __restrict__ b0_w, const float* __restrict__ b0_b, const float* __restrict__ b0_a,
    const float* __restrict__ b1_w, const float* __restrict__ b1_b,
    const float* __restrict__ b2_w, const float* __restrict__ b2_b,
    const float* __restrict__ b3_w, const float* __restrict__ b3_b,
    const float* __restrict__ b4_w, const float* __restrict__ b4_b,
    const float* __restrict__ b5_a,
    const float* __restrict__ b6_w, const float* __restrict__ b6_b, const float* __restrict__ b6_a,
    const float* __restrict__ tail_w, const float* __restrict__ tail_b,
    float* __restrict__ out)
{
    extern __shared__ float sm[];
    const int tid  = threadIdx.x;
    const int lane = tid & 31;
    const int warp = tid >> 5;
    const int b    = blockIdx.x;

    // ---- zero padded activation buffers + input region ----
    for (int i = tid; i < 27744 + 3888; i += TPB) sm[i] = 0.f;

    // ---- stage input / head+shrink weights ----
    const float* xin = x + b * 3 * 32 * 32;
    for (int i = tid; i < 3 * 32 * 32; i += TPB) {
        int c = i >> 10, r = i & 1023, yy = r >> 5, xx = r & 31;
        sm[XP + (c * 36 + yy + 2) * 36 + xx + 2] = xin[i];
    }
    for (int i = tid; i < 56 * 76; i += TPB) {
        int d = i / 76, k = i % 76;
        sm[HWS + i] = (k < 75) ? head_w[d * 75 + k] : 0.f;
    }
    if (tid < 56) { sm[HEADB + tid] = head_b[tid]; sm[HEADA + tid] = head_a[tid]; }
    for (int i = tid; i < 672; i += TPB) {
        int d = i / 12, s_ = i % 12;
        sm[B0W + i] = b0_w[s_ * 56 + d];   // transposed [d][s]
    }
    if (tid < 12) { sm[B0B + tid] = b0_b[tid]; sm[B0A + tid] = b0_a[tid]; }
    __syncthreads();

    // ================= Phase A: head(5x5)+PReLU fused with shrink(1x1)+PReLU =================
#pragma unroll 1
    for (int task = tid; task < 1024; task += TPB) {
        const int yy = task >> 5;
        const int xx = task & 31;
        ull win2[38];
#pragma unroll
        for (int i = 0; i < 38; i++) {
            const int f0 = 2 * i, f1 = 2 * i + 1;
            const int c0 = f0 / 25, r0 = f0 % 25;
            float e0 = sm[XP + (c0 * 36 + yy + r0 / 5) * 36 + xx + r0 % 5];
            float e1 = 0.f;
            if (f1 < 75) {
                const int c1 = f1 / 25, r1 = f1 % 25;
                e1 = sm[XP + (c1 * 36 + yy + r1 / 5) * 36 + xx + r1 % 5];
            }
            win2[i] = pk(e0, e1);
        }

        ull acc2[6];
#pragma unroll
        for (int p = 0; p < 6; p++)
            acc2[p] = pk(sm[B0B + 2 * p], sm[B0B + 2 * p + 1]);

        for (int d = 0; d < 56; d++) {
            const ulonglong2* wp = (const ulonglong2*)&sm[HWS + d * 76];
            ull t0 = 0ull, t1 = 0ull;
#pragma unroll
            for (int k = 0; k < 19; k++) {
                const ulonglong2 w = wp[k];
                fma2(t0, win2[2 * k], w.x);
                fma2(t1, win2[2 * k + 1], w.y);
            }
            float2 fa = upk(t0), fb = upk(t1);
            float t = (fa.x + fa.y) + (fb.x + fb.y) + sm[HEADB + d];
            t = (t >= 0.f) ? t : sm[HEADA + d] * t;
            const ull tt = pk(t, t);
            const ulonglong2* bp = (const ulonglong2*)&sm[B0W + d * 12];
            const ulonglong2 q0 = bp[0], q1 = bp[1], q2 = bp[2];
            fma2(acc2[0], tt, q0.x); fma2(acc2[1], tt, q0.y);
            fma2(acc2[2], tt, q1.x); fma2(acc2[3], tt, q1.y);
            fma2(acc2[4], tt, q2.x); fma2(acc2[5], tt, q2.y);
        }
#pragma unroll
        for (int p = 0; p < 6; p++) {
            float2 v = upk(acc2[p]);
            float v0 = v.x, v1 = v.y;
            v0 = (v0 >= 0.f) ? v0 : sm[B0A + 2 * p] * v0;
            v1 = (v1 >= 0.f) ? v1 : sm[B0A + 2 * p + 1] * v1;
            sm[H0 + ((2 * p) * 34 + yy + 1) * 34 + xx + 1] = v0;
            sm[H0 + ((2 * p + 1) * 34 + yy + 1) * 34 + xx + 1] = v1;
        }
    }
    __syncthreads();

    // ================= Phase B: four 3x3 (12->12) layers =================
    conv3x3_12<false>(sm, H0, H1, b1_w, b1_b, b5_a);
    conv3x3_12<false>(sm, H1, H0, b2_w, b2_b, b5_a);
    conv3x3_12<false>(sm, H0, H1, b3_w, b3_b, b5_a);
    conv3x3_12<true >(sm, H1, H0, b4_w, b4_b, b5_a);   // h5 ends in H0

    // ================= Phase C/D setup =================
    for (int i = tid; i < 13608; i += TPB) {
        // tail_w [ic56][oc3][ky9][kx9] -> smem [ky*9+kx][oc][ic]
        int ic = i / 243, rem = i % 243, oc = rem / 81, kk = rem % 81;
        sm[TWS + (kk * 3 + oc) * 56 + ic] = tail_w[i];
    }
    for (int i = tid; i < 672; i += TPB) sm[B6W + i] = b6_w[i];
    if (tid < 56) { sm[B6B + tid] = b6_b[tid]; sm[B6A + tid] = b6_a[tid]; }
    if (tid < 3)  sm[TAILB + tid] = tail_b[tid];
    __syncthreads();

    float* op = out + b * 3 * 64 * 64;

    const int cls = warp & 3;               // (pyr = cls>>1, pxc = cls&1)
    const int grp = warp >> 2;              // ic group 0..4
    const int cs  = grp * 3;                // [3,3,3,3,2] ic4 per group
    const int ce  = (grp < 4) ? cs + 3 : 14;

    // 4 strips of 16 output rows each
    for (int s = 0; s < 4; s++) {
        const int iy0 = 8 * s - 2;

        // ---- Phase C: g strip = PReLU(expand 1x1); [r12][x36][ic60], incl. zero padding ----
        for (int task = tid; task < 12 * 36; task += TPB) {
            const int r = task / 36, xb = task % 36;
            const int iy = iy0 + r;
            float* gq = &sm[GBUF + (r * 36 + xb) * 60];
            const int xx = xb - 2;
            if (iy >= 0 && iy < 32 && xx >= 0 && xx < 32) {
                ull hv2[6];
#pragma unroll
                for (int p = 0; p < 6; p++)
                    hv2[p] = pk(sm[H0 + ((2 * p) * 34 + iy + 1) * 34 + xx + 1],
                                sm[H0 + ((2 * p + 1) * 34 + iy + 1) * 34 + xx + 1]);
                for (int ic4 = 0; ic4 < 14; ic4++) {
                    float4 o;
#pragma unroll
                    for (int u = 0; u < 4; u++) {
                        const int ic = ic4 * 4 + u;
                        const ulonglong2* wp = (const ulonglong2*)&sm[B6W + ic * 12];
                        const ulonglong2 q0 = wp[0], q1 = wp[1], q2 = wp[2];
                        ull aA = 0ull, aB = 0ull;
                        fma2(aA, hv2[0], q0.x); fma2(aB, hv2[1], q0.y);
                        fma2(aA, hv2[2], q1.x); fma2(aB, hv2[3], q1.y);
                        fma2(aA, hv2[4], q2.x); fma2(aB, hv2[5], q2.y);
                        float2 fa = upk(aA), fb = upk(aB);
                        float t = (fa.x + fa.y) + (fb.x + fb.y) + sm[B6B + ic];
                        t = (t >= 0.f) ? t : sm[B6A + ic] * t;
                        (&o.x)[u] = t;
                    }
                    *(float4*)&gq[ic4 * 4] = o;
                }
            } else {
                const float4 z = {0.f, 0.f, 0.f, 0.f};
                for (int ic4 = 0; ic4 < 14; ic4++) *(float4*)&gq[ic4 * 4] = z;
            }
        }
        __syncthreads();

        // ---- Phase D: deconv with rolling register window ----
        ull acc[8][3];
#pragma unroll
        for (int t = 0; t < 8; t++)
#pragma unroll
            for (int oc = 0; oc < 3; oc++) acc[t][oc] = 0ull;

        if      (cls == 0) deconv_cls<0, 0>(sm, lane, cs, ce, acc);
        else if (cls == 1) deconv_cls<0, 1>(sm, lane, cs, ce, acc);
        else if (cls == 2) deconv_cls<1, 0>(sm, lane, cs, ce, acc);
        else               deconv_cls<1, 1>(sm, lane, cs, ce, acc);
        __syncthreads();   // all g reads done before scratch reuse

        // partials into GBUF-as-scratch: [grp][cls][t][oc][lane]
#pragma unroll
        for (int t = 0; t < 8; t++)
#pragma unroll
            for (int oc = 0; oc < 3; oc++) {
                float2 f = upk(acc[t][oc]);
                sm[GBUF + ((grp * 4 + cls) * 8 + t) * 96 + oc * 32 + lane] = f.x + f.y;
            }
        __syncthreads();

        // reduce + store
        for (int v = tid; v < 3072; v += TPB) {
            const int ln = v & 31;
            const int q  = v >> 5;
            const int oc = q % 3;
            const int q2 = q / 3;
            const int t  = q2 & 7;
            const int cl = q2 >> 3;
            const int base = (cl * 8 + t) * 96 + oc * 32 + ln;
            float val = sm[TAILB + oc];
#pragma unroll
            for (int g5 = 0; g5 < 5; g5++)
                val += sm[GBUF + base + g5 * 3072];
            const int pyr = cl >> 1, pxc = cl & 1;
            const int oy = 16 * s + 2 * t + pyr;
            const int ox = 2 * ln + pxc;
            op[(oc * 64 + oy) * 64 + ox] = val;
        }
        __syncthreads();
    }
}

extern "C" void kernel_launch(void* const* d_in, const int* in_sizes, int n_in,
                              void* d_out, int out_size)
{
    (void)in_sizes; (void)n_in; (void)out_size;
    cudaFuncSetAttribute(fsrcnn_fused_kernel,
                         cudaFuncAttributeMaxDynamicSharedMemorySize, SMEM_BYTES);
    fsrcnn_fused_kernel<<<NBLK, TPB, SMEM_BYTES>>>(
        (const float*)d_in[0],
        (const float*)d_in[1], (const float*)d_in[2], (const float*)d_in[3],
        (const float*)d_in[4], (const float*)d_in[5], (const float*)d_in[6],
        (const float*)d_in[7], (const float*)d_in[8],
        (const float*)d_in[9], (const float*)d_in[10],
        (const float*)d_in[11], (const float*)d_in[12],
        (const float*)d_in[13], (const float*)d_in[14],
        (const float*)d_in[15],
        (const float*)d_in[16], (const float*)d_in[17], (const float*)d_in[18],
        (const float*)d_in[19], (const float*)d_in[20],
        (float*)d_out);
}

// round 8
// speedup vs baseline: 1.3524x; 1.3524x over previous
#include <cuda_runtime.h>

#define TPB 512
#define NBLK 1024

typedef unsigned long long ull;

// ---- packed f32x2 helpers ----
__device__ __forceinline__ ull pk(float a, float b) {
    ull r; asm("mov.b64 %0,{%1,%2};" : "=l"(r) : "f"(a), "f"(b)); return r;
}
__device__ __forceinline__ void fma2(ull& d, ull a, ull b) {
    asm("fma.rn.f32x2 %0,%1,%2,%0;" : "+l"(d) : "l"(a), "l"(b));
}
__device__ __forceinline__ float2 upk(ull v) {
    float2 f; asm("mov.b64 {%0,%1},%2;" : "=f"(f.x), "=f"(f.y) : "l"(v)); return f;
}

// ---- dynamic smem layout (float offsets) ----
#define H0    0            // 12x34x34 padded activation ping (13872)
#define H1    13872        // pong; later transposed tail weights
#define TWS   H1           // [ky*9+kx][oc][ic56] (13608)
#define R2    27744
// phase A
#define XP    (R2)         // 3x36x36 padded input (3888)
#define HWS   (R2+3888)    // head weights padded [56][76] (4256)
#define HEADB (R2+8144)
#define HEADA (R2+8200)
#define B0W   (R2+8256)    // transposed [d56][12] (672)
#define B0B   (R2+8928)
#define B0A   (R2+8940)
// phase B
#define WSC   (R2)         // transposed [ic12][k9][oc12] (1296)
#define BSC   (R2+1296)
#define ASC   (R2+1308)
// phase C/D
#define GBUF  (R2)         // g strip [12 rows][36 x][60 ic-pad] (25920); also reduce scratch
#define B6B   (R2+25920)
#define B6A   (R2+25976)
#define TAILB (R2+26032)
#define B6W   (R2+26048)   // [oc56][12] (672)
#define SMEM_FLOATS (R2+26720)
#define SMEM_BYTES  (SMEM_FLOATS*4)

// ================= Phase B: 3x3 conv 12->12, 2 rows/thread, f32x2 =================
template<bool ACT>
__device__ __forceinline__ void conv3x3_12(float* sm, int inOff, int outOff,
    const float* __restrict__ wg, const float* __restrict__ bg,
    const float* __restrict__ ag)
{
    const int tid = threadIdx.x;
    // stage weights transposed: [ic][k][oc]
    for (int i = tid; i < 1296; i += TPB) {
        int oc = i % 12, k = (i / 12) % 9, ic = i / 108;
        sm[WSC + ic * 108 + k * 12 + oc] = wg[(oc * 12 + ic) * 9 + k];
    }
    if (tid < 12) { sm[BSC + tid] = bg[tid]; if (ACT) sm[ASC + tid] = ag[tid]; }
    __syncthreads();

    const int xx = tid & 31;
    const int y0 = (tid >> 5) * 2;

    ull acc[2][6];
#pragma unroll
    for (int j = 0; j < 2; j++)
#pragma unroll
        for (int p = 0; p < 6; p++)
            acc[j][p] = pk(sm[BSC + 2 * p], sm[BSC + 2 * p + 1]);

    for (int ic = 0; ic < 12; ic++) {
        float win[4][3];
#pragma unroll
        for (int ry = 0; ry < 4; ry++)
#pragma unroll
            for (int cx = 0; cx < 3; cx++)
                win[ry][cx] = sm[inOff + (ic * 34 + y0 + ry) * 34 + xx + cx];
#pragma unroll
        for (int k = 0; k < 9; k++) {
            const int ky = k / 3, kx = k % 3;
            const ulonglong2* wp = (const ulonglong2*)&sm[WSC + ic * 108 + k * 12];
            const ulonglong2 wA = wp[0], wB = wp[1], wC = wp[2];
#pragma unroll
            for (int j = 0; j < 2; j++) {
                const float v = win[j + ky][kx];
                const ull vv = pk(v, v);
                fma2(acc[j][0], vv, wA.x); fma2(acc[j][1], vv, wA.y);
                fma2(acc[j][2], vv, wB.x); fma2(acc[j][3], vv, wB.y);
                fma2(acc[j][4], vv, wC.x); fma2(acc[j][5], vv, wC.y);
            }
        }
    }
    __syncthreads();
#pragma unroll
    for (int j = 0; j < 2; j++)
#pragma unroll
        for (int p = 0; p < 6; p++) {
            float2 v = upk(acc[j][p]);
            float v0 = v.x, v1 = v.y;
            if (ACT) {
                v0 = (v0 >= 0.f) ? v0 : sm[ASC + 2 * p] * v0;
                v1 = (v1 >= 0.f) ? v1 : sm[ASC + 2 * p + 1] * v1;
            }
            sm[outOff + ((2 * p) * 34 + y0 + j + 1) * 34 + xx + 1] = v0;
            sm[outOff + ((2 * p + 1) * 34 + y0 + j + 1) * 34 + xx + 1] = v1;
        }
    __syncthreads();
}

// ================= Phase D worker: pipelined weights + rolling row window =================
// Prefetch goes into TEMP registers before the FMA block; commit AFTER the block
// (slot (3-a)&7 holds row 11-a, still live at t=7 of the current step).
template<int PYR, int PXC>
__device__ __forceinline__ void deconv_cls(const float* sm, int lane, int cs, int ce,
                                           ull (&acc)[8][3])
{
    constexpr int A = PYR ? 4 : 5;   // #ky taps
    constexpr int C = PXC ? 4 : 5;   // #kx taps
    for (int ic4 = cs; ic4 < ce; ic4++) {
        const int gofs = ic4 * 4;
#pragma unroll
        for (int c = 0; c < C; c++) {
            const int kx = PXC + 2 * c;
            const int d  = 4 - c;
            const float* gb  = &sm[GBUF + (lane + d) * 60 + gofs];
            const float* twb = &sm[TWS + kx * 3 * 56 + gofs];   // + ky*9*3*56 selects ky
            ulonglong2 Gw[8];
#pragma unroll
            for (int rr = 4; rr <= 11; rr++)
                Gw[rr & 7] = *(const ulonglong2*)&gb[rr * 36 * 60];
            // preload weights for first ky step
            ulonglong2 w0 = *(const ulonglong2*)&twb[PYR * 9 * 56 * 3];
            ulonglong2 w1 = *(const ulonglong2*)&twb[PYR * 9 * 56 * 3 + 56];
            ulonglong2 w2 = *(const ulonglong2*)&twb[PYR * 9 * 56 * 3 + 112];
#pragma unroll
            for (int a = 0; a < A; a++) {
                // ---- prefetch next step's data into temps (issue early) ----
                ulonglong2 wn0, wn1, wn2, gnext;
                if (a < A - 1) {
                    const int kyn = PYR + 2 * (a + 1);
                    wn0 = *(const ulonglong2*)&twb[kyn * 9 * 56 * 3];
                    wn1 = *(const ulonglong2*)&twb[kyn * 9 * 56 * 3 + 56];
                    wn2 = *(const ulonglong2*)&twb[kyn * 9 * 56 * 3 + 112];
                    gnext = *(const ulonglong2*)&gb[(3 - a) * 36 * 60];
                }
                // ---- fma block under current weights/window ----
#pragma unroll
                for (int t = 0; t < 8; t++) {
                    const ulonglong2 g = Gw[(t + 4 - a) & 7];
                    fma2(acc[t][0], g.x, w0.x); fma2(acc[t][0], g.y, w0.y);
                    fma2(acc[t][1], g.x, w1.x); fma2(acc[t][1], g.y, w1.y);
                    fma2(acc[t][2], g.x, w2.x); fma2(acc[t][2], g.y, w2.y);
                }
                // ---- commit prefetched values (after last use of old slot) ----
                if (a < A - 1) {
                    w0 = wn0; w1 = wn1; w2 = wn2;
                    Gw[(3 - a) & 7] = gnext;
                }
            }
        }
    }
}

__global__ __launch_bounds__(TPB, 1)
void fsrcnn_fused_kernel(
    const float* __restrict__ x,
    const float* __restrict__ head_w, const float* __restrict__ head_b, const float* __restrict__ head_a,
    const float* __restrict__ b0_w, const float* __restrict__ b0_b, const float* __restrict__ b0_a,
    const float* __restrict__ b1_w, const float* __restrict__ b1_b,
    const float* __restrict__ b2_w, const float* __restrict__ b2_b,
    const float* __restrict__ b3_w, const float* __restrict__ b3_b,
    const float* __restrict__ b4_w, const float* __restrict__ b4_b,
    const float* __restrict__ b5_a,
    const float* __restrict__ b6_w, const float* __restrict__ b6_b, const float* __restrict__ b6_a,
    const float* __restrict__ tail_w, const float* __restrict__ tail_b,
    float* __restrict__ out)
{
    extern __shared__ float sm[];
    const int tid  = threadIdx.x;
    const int lane = tid & 31;
    const int warp = tid >> 5;
    const int b    = blockIdx.x;

    // ---- zero padded activation buffers + input region ----
    for (int i = tid; i < 27744 + 3888; i += TPB) sm[i] = 0.f;

    // ---- stage input / head+shrink weights ----
    const float* xin = x + b * 3 * 32 * 32;
    for (int i = tid; i < 3 * 32 * 32; i += TPB) {
        int c = i >> 10, r = i & 1023, yy = r >> 5, xx = r & 31;
        sm[XP + (c * 36 + yy + 2) * 36 + xx + 2] = xin[i];
    }
    for (int i = tid; i < 56 * 76; i += TPB) {
        int d = i / 76, k = i % 76;
        sm[HWS + i] = (k < 75) ? head_w[d * 75 + k] : 0.f;
    }
    if (tid < 56) { sm[HEADB + tid] = head_b[tid]; sm[HEADA + tid] = head_a[tid]; }
    for (int i = tid; i < 672; i += TPB) {
        int d = i / 12, s_ = i % 12;
        sm[B0W + i] = b0_w[s_ * 56 + d];   // transposed [d][s]
    }
    if (tid < 12) { sm[B0B + tid] = b0_b[tid]; sm[B0A + tid] = b0_a[tid]; }
    __syncthreads();

    // ================= Phase A: head(5x5)+PReLU fused with shrink(1x1)+PReLU =================
    {
        const int xx = lane;
        const int y0 = warp * 2;
#pragma unroll 1
        for (int j = 0; j < 2; j++) {
            const int yy = y0 + j;
            ull win2[38];
#pragma unroll
            for (int i = 0; i < 38; i++) {
                const int f0 = 2 * i, f1 = 2 * i + 1;
                const int c0 = f0 / 25, r0 = f0 % 25;
                float e0 = sm[XP + (c0 * 36 + yy + r0 / 5) * 36 + xx + r0 % 5];
                float e1 = 0.f;
                if (f1 < 75) {
                    const int c1 = f1 / 25, r1 = f1 % 25;
                    e1 = sm[XP + (c1 * 36 + yy + r1 / 5) * 36 + xx + r1 % 5];
                }
                win2[i] = pk(e0, e1);
            }

            ull acc2[6];
#pragma unroll
            for (int p = 0; p < 6; p++)
                acc2[p] = pk(sm[B0B + 2 * p], sm[B0B + 2 * p + 1]);

            // interleaved d-pairs: 4 independent 19-deep chains
#pragma unroll 1
            for (int d = 0; d < 56; d += 2) {
                const ulonglong2* wpA = (const ulonglong2*)&sm[HWS + d * 76];
                const ulonglong2* wpB = (const ulonglong2*)&sm[HWS + (d + 1) * 76];
                ull t0a = 0ull, t1a = 0ull, t0b = 0ull, t1b = 0ull;
#pragma unroll
                for (int k = 0; k < 19; k++) {
                    const ulonglong2 wa = wpA[k];
                    const ulonglong2 wb = wpB[k];
                    fma2(t0a, win2[2 * k], wa.x);
                    fma2(t1a, win2[2 * k + 1], wa.y);
                    fma2(t0b, win2[2 * k], wb.x);
                    fma2(t1b, win2[2 * k + 1], wb.y);
                }
                float2 fa = upk(t0a), fb = upk(t1a);
                float2 ga = upk(t0b), gb2 = upk(t1b);
                float tA = (fa.x + fa.y) + (fb.x + fb.y) + sm[HEADB + d];
                float tB = (ga.x + ga.y) + (gb2.x + gb2.y) + sm[HEADB + d + 1];
                tA = (tA >= 0.f) ? tA : sm[HEADA + d] * tA;
                tB = (tB >= 0.f) ? tB : sm[HEADA + d + 1] * tB;
                const ull ttA = pk(tA, tA);
                const ull ttB = pk(tB, tB);
                const ulonglong2* bpA = (const ulonglong2*)&sm[B0W + d * 12];
                const ulonglong2* bpB = (const ulonglong2*)&sm[B0W + (d + 1) * 12];
                const ulonglong2 qa0 = bpA[0], qa1 = bpA[1], qa2 = bpA[2];
                const ulonglong2 qb0 = bpB[0], qb1 = bpB[1], qb2 = bpB[2];
                fma2(acc2[0], ttA, qa0.x); fma2(acc2[1], ttA, qa0.y);
                fma2(acc2[2], ttA, qa1.x); fma2(acc2[3], ttA, qa1.y);
                fma2(acc2[4], ttA, qa2.x); fma2(acc2[5], ttA, qa2.y);
                fma2(acc2[0], ttB, qb0.x); fma2(acc2[1], ttB, qb0.y);
                fma2(acc2[2], ttB, qb1.x); fma2(acc2[3], ttB, qb1.y);
                fma2(acc2[4], ttB, qb2.x); fma2(acc2[5], ttB, qb2.y);
            }
#pragma unroll
            for (int p = 0; p < 6; p++) {
                float2 v = upk(acc2[p]);
                float v0 = v.x, v1 = v.y;
                v0 = (v0 >= 0.f) ? v0 : sm[B0A + 2 * p] * v0;
                v1 = (v1 >= 0.f) ? v1 : sm[B0A + 2 * p + 1] * v1;
                sm[H0 + ((2 * p) * 34 + yy + 1) * 34 + xx + 1] = v0;
                sm[H0 + ((2 * p + 1) * 34 + yy + 1) * 34 + xx + 1] = v1;
            }
        }
    }
    __syncthreads();

    // ================= Phase B: four 3x3 (12->12) layers =================
    conv3x3_12<false>(sm, H0, H1, b1_w, b1_b, b5_a);
    conv3x3_12<false>(sm, H1, H0, b2_w, b2_b, b5_a);
    conv3x3_12<false>(sm, H0, H1, b3_w, b3_b, b5_a);
    conv3x3_12<true >(sm, H1, H0, b4_w, b4_b, b5_a);   // h5 ends in H0

    // ================= Phase C/D setup =================
    for (int i = tid; i < 13608; i += TPB) {
        // tail_w [ic56][oc3][ky9][kx9] -> smem [ky*9+kx][oc][ic]
        int ic = i / 243, rem = i % 243, oc = rem / 81, kk = rem % 81;
        sm[TWS + (kk * 3 + oc) * 56 + ic] = tail_w[i];
    }
    for (int i = tid; i < 672; i += TPB) sm[B6W + i] = b6_w[i];
    if (tid < 56) { sm[B6B + tid] = b6_b[tid]; sm[B6A + tid] = b6_a[tid]; }
    if (tid < 3)  sm[TAILB + tid] = tail_b[tid];
    __syncthreads();

    float* op = out + b * 3 * 64 * 64;

    const int cls = warp & 3;               // (pyr = cls>>1, pxc = cls&1)
    const int grp = warp >> 2;              // ic group 0..3
    const int cs  = (grp == 0) ? 0 : (grp == 1) ? 4 : (grp == 2) ? 8 : 11;
    const int ce  = cs + ((grp < 2) ? 4 : 3);

    // 4 strips of 16 output rows each
    for (int s = 0; s < 4; s++) {
        const int iy0 = 8 * s - 2;

        // ---- Phase C: g strip = PReLU(expand 1x1); [r12][x36][ic60], incl. zero padding ----
        for (int task = tid; task < 12 * 36; task += TPB) {
            const int r = task / 36, xb = task % 36;
            const int iy = iy0 + r;
            float* gq = &sm[GBUF + (r * 36 + xb) * 60];
            const int xx = xb - 2;
            if (iy >= 0 && iy < 32 && xx >= 0 && xx < 32) {
                ull hv2[6];
#pragma unroll
                for (int p = 0; p < 6; p++)
                    hv2[p] = pk(sm[H0 + ((2 * p) * 34 + iy + 1) * 34 + xx + 1],
                                sm[H0 + ((2 * p + 1) * 34 + iy + 1) * 34 + xx + 1]);
                for (int ic4 = 0; ic4 < 14; ic4++) {
                    float4 o;
#pragma unroll
                    for (int u = 0; u < 4; u++) {
                        const int ic = ic4 * 4 + u;
                        const ulonglong2* wp = (const ulonglong2*)&sm[B6W + ic * 12];
                        const ulonglong2 q0 = wp[0], q1 = wp[1], q2 = wp[2];
                        ull aA = 0ull, aB = 0ull;
                        fma2(aA, hv2[0], q0.x); fma2(aB, hv2[1], q0.y);
                        fma2(aA, hv2[2], q1.x); fma2(aB, hv2[3], q1.y);
                        fma2(aA, hv2[4], q2.x); fma2(aB, hv2[5], q2.y);
                        float2 fa = upk(aA), fb = upk(aB);
                        float t = (fa.x + fa.y) + (fb.x + fb.y) + sm[B6B + ic];
                        t = (t >= 0.f) ? t : sm[B6A + ic] * t;
                        (&o.x)[u] = t;
                    }
                    *(float4*)&gq[ic4 * 4] = o;
                }
            } else {
                const float4 z = {0.f, 0.f, 0.f, 0.f};
                for (int ic4 = 0; ic4 < 14; ic4++) *(float4*)&gq[ic4 * 4] = z;
            }
        }
        __syncthreads();

        // ---- Phase D: deconv with pipelined rolling register window ----
        ull acc[8][3];
#pragma unroll
        for (int t = 0; t < 8; t++)
#pragma unroll
            for (int oc = 0; oc < 3; oc++) acc[t][oc] = 0ull;

        if      (cls == 0) deconv_cls<0, 0>(sm, lane, cs, ce, acc);
        else if (cls == 1) deconv_cls<0, 1>(sm, lane, cs, ce, acc);
        else if (cls == 2) deconv_cls<1, 0>(sm, lane, cs, ce, acc);
        else               deconv_cls<1, 1>(sm, lane, cs, ce, acc);
        __syncthreads();   // all g reads done before scratch reuse

        // partials into GBUF-as-scratch: [grp][cls][t][oc][lane]
#pragma unroll
        for (int t = 0; t < 8; t++)
#pragma unroll
            for (int oc = 0; oc < 3; oc++) {
                float2 f = upk(acc[t][oc]);
                sm[GBUF + ((grp * 4 + cls) * 8 + t) * 96 + oc * 32 + lane] = f.x + f.y;
            }
        __syncthreads();

        // reduce + store
        for (int v = tid; v < 3072; v += TPB) {
            const int ln = v & 31;
            const int q  = v >> 5;
            const int oc = q % 3;
            const int q2 = q / 3;
            const int t  = q2 & 7;
            const int cl = q2 >> 3;
            const int base = (cl * 8 + t) * 96 + oc * 32 + ln;
            float val = sm[GBUF + base] + sm[GBUF + base + 3072]
                      + sm[GBUF + base + 6144] + sm[GBUF + base + 9216]
                      + sm[TAILB + oc];
            const int pyr = cl >> 1, pxc = cl & 1;
            const int oy = 16 * s + 2 * t + pyr;
            const int ox = 2 * ln + pxc;
            op[(oc * 64 + oy) * 64 + ox] = val;
        }
        __syncthreads();
    }
}

extern "C" void kernel_launch(void* const* d_in, const int* in_sizes, int n_in,
                              void* d_out, int out_size)
{
    (void)in_sizes; (void)n_in; (void)out_size;
    cudaFuncSetAttribute(fsrcnn_fused_kernel,
                         cudaFuncAttributeMaxDynamicSharedMemorySize, SMEM_BYTES);
    fsrcnn_fused_kernel<<<NBLK, TPB, SMEM_BYTES>>>(
        (const float*)d_in[0],
        (const float*)d_in[1], (const float*)d_in[2], (const float*)d_in[3],
        (const float*)d_in[4], (const float*)d_in[5], (const float*)d_in[6],
        (const float*)d_in[7], (const float*)d_in[8],
        (const float*)d_in[9], (const float*)d_in[10],
        (const float*)d_in[11], (const float*)d_in[12],
        (const float*)d_in[13], (const float*)d_in[14],
        (const float*)d_in[15],
        (const float*)d_in[16], (const float*)d_in[17], (const float*)d_in[18],
        (const float*)d_in[19], (const float*)d_in[20],
        (float*)d_out);
}